// round 1
// baseline (speedup 1.0000x reference)
#include <cuda_runtime.h>
#include <cuda_bf16.h>
#include <cstdint>

#define BB 64
#define II 128
#define AA 16
#define HH 1024
#define BH (BB*HH)

// scratch (static __device__ — no allocations)
__device__ float g_so[BH];              // sign_j * output[b,j]
__device__ float g_ff[BH];              // b_h + relu(x)@|W_x|^T + relu(aux)@|W_aux|^T
__device__ unsigned int g_gq[HH*HH];    // packed bf16: lo = 0.02*|W_h|, hi = |kappa|

// ---------------- prep: pack (0.02*|W_h|, |kappa|) as bf16x2 ----------------
__global__ void prep_gq(const float* __restrict__ Wh, const float* __restrict__ kap) {
    int idx = blockIdx.x * blockDim.x + threadIdx.x;
    if (idx >= HH * HH) return;
    float g = 0.02f * fabsf(Wh[idx]);
    float q = fabsf(kap[idx]);
    unsigned short gs = __bfloat16_as_ushort(__float2bfloat16_rn(g));
    unsigned short qs = __bfloat16_as_ushort(__float2bfloat16_rn(q));
    g_gq[idx] = (unsigned int)gs | ((unsigned int)qs << 16);
}

// ---------------- prep: signed output + feedforward drive ----------------
__global__ void prep_soff(const float* __restrict__ x, const float* __restrict__ outp,
                          const float* __restrict__ aux,
                          const float* __restrict__ Wx, const float* __restrict__ Waux,
                          const float* __restrict__ bh, const float* __restrict__ mask) {
    int idx = blockIdx.x * blockDim.x + threadIdx.x;
    if (idx >= BH) return;
    int b = idx >> 10;
    int i = idx & (HH - 1);
    // mask_h[r, j] = sign_j for any r != j (zero diagonal) -> read row (i+1)%H
    float sgn = mask[((i + 1) & (HH - 1)) * HH + i];
    g_so[idx] = sgn * outp[idx];

    float acc = bh[i];
    const float* wr = Wx + i * II;
    const float* xr = x + b * II;
#pragma unroll 8
    for (int k = 0; k < II; k++) acc += fmaxf(xr[k], 0.f) * fabsf(wr[k]);
    const float* wa = Waux + i * AA;
    const float* ar = aux + b * AA;
#pragma unroll
    for (int k = 0; k < AA; k++) acc += fmaxf(ar[k], 0.f) * fabsf(wa[k]);
    g_ff[idx] = acc;
}

// ---------------- pass 1: new_state / new_output (warp-per-row matvec) ----------------
__global__ __launch_bounds__(256) void k_state(const float* __restrict__ wh,
                                               const float* __restrict__ state,
                                               float* __restrict__ out_state,
                                               float* __restrict__ out_output) {
    __shared__ float so_sh[HH];
    const int warp = threadIdx.x >> 5;
    const int lane = threadIdx.x & 31;
    const int row0 = blockIdx.x * 8;          // 8 warps = 8 rows, all same batch (H % 8 == 0)
    const int b = row0 >> 10;
    const int row = row0 + warp;
    const int i = row & (HH - 1);

    for (int k = threadIdx.x; k < HH; k += 256) so_sh[k] = g_so[(b << 10) + k];
    __syncthreads();

    const float4* w4 = (const float4*)(wh + (size_t)row * HH);
    const float4* s4 = (const float4*)so_sh;
    float acc = 0.f;
#pragma unroll
    for (int k = 0; k < 8; k++) {
        float4 w = w4[lane + 32 * k];
        float4 s = s4[lane + 32 * k];
        acc += w.x * s.x + w.y * s.y + w.z * s.z + w.w * s.w;
    }
#pragma unroll
    for (int off = 16; off; off >>= 1) acc += __shfl_down_sync(0xffffffffu, acc, off);

    if (lane == 0) {
        float diag = wh[(size_t)row * HH + i] * so_sh[i];   // remove diagonal (mask=0 there)
        float total = acc - diag + g_ff[row];
        float ns = 0.8f * state[row] + 0.2f * total;
        out_state[row] = ns;
        out_output[row] = ns > 0.f ? tanhf(ns) : 0.f;       // retanh
    }
}

// ---------------- pass 2: plasticity update (element-wise stream) ----------------
__global__ __launch_bounds__(256) void k_plast(const float* __restrict__ wh,
                                               const float* __restrict__ da,
                                               const float* __restrict__ newout,
                                               float* __restrict__ out_w) {
    const int row = blockIdx.x;               // (b,i)
    const int b = row >> 10;
    const int i = row & (HH - 1);
    const float no_i = newout[row];
    const float coef = 0.02f * da[b] * no_i;  // DT * da * new_output_i

    const int t = threadIdx.x;                // 256 threads x 4 cols
    const size_t base = (size_t)row * HH + 4 * t;

    float4 w = __ldcs((const float4*)(wh + base));
    uint4 gq = *(const uint4*)(g_gq + i * HH + 4 * t);
    float4 no = *(const float4*)(newout + (b << 10) + 4 * t);

    float4 r;
    {
        float g = __bfloat162float(__ushort_as_bfloat16((unsigned short)(gq.x & 0xffff)));
        float q = __bfloat162float(__ushort_as_bfloat16((unsigned short)(gq.x >> 16)));
        r.x = fminf(fmaxf(g + 0.98f * w.x + coef * q * no.x, 0.f), 1.f);
    }
    {
        float g = __bfloat162float(__ushort_as_bfloat16((unsigned short)(gq.y & 0xffff)));
        float q = __bfloat162float(__ushort_as_bfloat16((unsigned short)(gq.y >> 16)));
        r.y = fminf(fmaxf(g + 0.98f * w.y + coef * q * no.y, 0.f), 1.f);
    }
    {
        float g = __bfloat162float(__ushort_as_bfloat16((unsigned short)(gq.z & 0xffff)));
        float q = __bfloat162float(__ushort_as_bfloat16((unsigned short)(gq.z >> 16)));
        r.z = fminf(fmaxf(g + 0.98f * w.z + coef * q * no.z, 0.f), 1.f);
    }
    {
        float g = __bfloat162float(__ushort_as_bfloat16((unsigned short)(gq.w & 0xffff)));
        float q = __bfloat162float(__ushort_as_bfloat16((unsigned short)(gq.w >> 16)));
        r.w = fminf(fmaxf(g + 0.98f * w.w + coef * q * no.w, 0.f), 1.f);
    }
    __stcs((float4*)(out_w + base), r);
}

extern "C" void kernel_launch(void* const* d_in, const int* in_sizes, int n_in,
                              void* d_out, int out_size) {
    const float* x      = (const float*)d_in[0];   // [B,I]
    const float* state  = (const float*)d_in[1];   // [B,H]
    const float* outp   = (const float*)d_in[2];   // [B,H]
    const float* wh     = (const float*)d_in[3];   // [B,H,H]
    const float* da     = (const float*)d_in[4];   // [B]
    const float* aux    = (const float*)d_in[5];   // [B,A]
    const float* Wx     = (const float*)d_in[6];   // [H,I]
    const float* Waux   = (const float*)d_in[7];   // [H,A]
    const float* Wh     = (const float*)d_in[8];   // [H,H]
    const float* bh     = (const float*)d_in[9];   // [H]
    const float* kappa  = (const float*)d_in[10];  // [H,H]
    const float* mask   = (const float*)d_in[11];  // [H,H]

    float* out_state  = (float*)d_out;                 // [B,H]
    float* out_output = (float*)d_out + BH;            // [B,H]
    float* out_w      = (float*)d_out + 2 * BH;        // [B,H,H]

    prep_gq<<<(HH * HH + 255) / 256, 256>>>(Wh, kappa);
    prep_soff<<<(BH + 255) / 256, 256>>>(x, outp, aux, Wx, Waux, bh, mask);
    k_state<<<BH / 8, 256>>>(wh, state, out_state, out_output);
    k_plast<<<BH, 256>>>(wh, da, out_output, out_w);
}